// round 3
// baseline (speedup 1.0000x reference)
#include <cuda_runtime.h>
#include <cuda_bf16.h>

// SoftIndex: per-row out[s] = cumsum_s( tanh(x[s] - x[s-1]) ), first diff = 0.
// x: [8192, 8192] fp32, out: same shape.
// R3: warp-per-row chunked scan. No __syncthreads, no smem. Each warp walks
// its row in 32 chunks of 256 elements (8/lane), carrying the running sum via
// shfl. Next chunk's loads are prefetched before current chunk's compute so
// every warp always has memory in flight -> continuous DRAM streaming.

#define S 8192
#define LPT 8                 // elements per lane per chunk
#define CHUNK 256             // 32 * LPT
#define NCHUNK 32             // S / CHUNK
#define WARPS_PER_CTA 8
#define THREADS 256

// tanh(d) = 1 - 2/(ex2(d * 2/ln2) + 1); exact saturation at +/-inf.
__device__ __forceinline__ float fast_tanh(float d)
{
    float e;
    asm("ex2.approx.f32 %0, %1;" : "=f"(e) : "f"(d * 2.885390081777927f));
    float r;
    asm("rcp.approx.f32 %0, %1;" : "=f"(r) : "f"(e + 1.0f));
    return fmaf(-2.0f, r, 1.0f);
}

__global__ __launch_bounds__(THREADS, 3)
void softindex_kernel(const float* __restrict__ x, float* __restrict__ out)
{
    const int wrow = blockIdx.x * WARPS_PER_CTA + (threadIdx.x >> 5);
    const unsigned lane = threadIdx.x & 31u;

    const float* __restrict__ xr   = x   + (size_t)wrow * S;
    float* __restrict__       orow = out + (size_t)wrow * S;

    const int lbase = (int)lane * LPT;

    // Prefetch chunk 0.
    float4 ca = __ldcs(reinterpret_cast<const float4*>(xr + lbase));
    float4 cb = __ldcs(reinterpret_cast<const float4*>(xr + lbase + 4));

    float carry      = 0.0f;  // cumsum through end of previous chunk
    float chunk_last = 0.0f;  // last x element of previous chunk (broadcast)

#pragma unroll 1
    for (int ch = 0; ch < NCHUNK; ch++) {
        // Prefetch next chunk before any compute of this chunk.
        float4 na = make_float4(0.f, 0.f, 0.f, 0.f);
        float4 nb = na;
        if (ch + 1 < NCHUNK) {
            const float* pn = xr + (ch + 1) * CHUNK + lbase;
            na = __ldcs(reinterpret_cast<const float4*>(pn));
            nb = __ldcs(reinterpret_cast<const float4*>(pn + 4));
        }

        float v[LPT] = {ca.x, ca.y, ca.z, ca.w, cb.x, cb.y, cb.z, cb.w};

        // Neighbor for this lane's first diff: previous lane's last element;
        // lane 0 uses previous chunk's last element (or v[0] -> diff 0 at row start).
        float prev = __shfl_up_sync(0xffffffffu, v[LPT - 1], 1);
        if (lane == 0u) prev = (ch == 0) ? v[0] : chunk_last;

        // Lane-local inclusive scan of tanh(diffs).
        float s[LPT];
        float run = 0.0f, p = prev;
#pragma unroll
        for (int i = 0; i < LPT; i++) {
            run += fast_tanh(v[i] - p);
            p = v[i];
            s[i] = run;
        }
        const float tot = run;

        // Warp inclusive scan of lane totals.
        float ws = tot;
#pragma unroll
        for (int off = 1; off < 32; off <<= 1) {
            float n = __shfl_up_sync(0xffffffffu, ws, off);
            if (lane >= (unsigned)off) ws += n;
        }

        const float prefix = carry + (ws - tot);   // exclusive for this lane

        float* po = orow + ch * CHUNK + lbase;
        __stcs(reinterpret_cast<float4*>(po),
               make_float4(prefix + s[0], prefix + s[1], prefix + s[2], prefix + s[3]));
        __stcs(reinterpret_cast<float4*>(po + 4),
               make_float4(prefix + s[4], prefix + s[5], prefix + s[6], prefix + s[7]));

        // Carry forward: total of this chunk = lane31's inclusive value.
        carry     += __shfl_sync(0xffffffffu, ws, 31);
        chunk_last  = __shfl_sync(0xffffffffu, v[LPT - 1], 31);

        ca = na;
        cb = nb;
    }
}

extern "C" void kernel_launch(void* const* d_in, const int* in_sizes, int n_in,
                              void* d_out, int out_size)
{
    const float* x = (const float*)d_in[0];
    float* out     = (float*)d_out;
    (void)in_sizes; (void)n_in; (void)out_size;

    softindex_kernel<<<S / WARPS_PER_CTA, THREADS>>>(x, out);
}

// round 4
// speedup vs baseline: 1.2872x; 1.2872x over previous
#include <cuda_runtime.h>
#include <cuda_bf16.h>

// SoftIndex: per-row out[s] = cumsum_s( tanh(x[s] - x[s-1]) ), first diff = 0.
// x: [8192, 8192] fp32, out: same shape.
// R4: persistent warps + dynamic row queue (kills wave quantization) and
// depth-2 register prefetch (2 KB/warp in flight, load-to-use ~2 chunk
// periods ~ DRAM latency). No smem, no __syncthreads.

#define S 8192
#define LPT 8                 // elements per lane per chunk
#define CHUNK 256             // 32 * LPT
#define NCHUNK 32             // S / CHUNK
#define THREADS 256
#define GRID 592              // ~4 CTAs/SM on 148 SMs; dynamic queue balances

__device__ unsigned int g_row_ctr;

__global__ void reset_ctr_kernel() { g_row_ctr = 0u; }

// tanh(d) = 1 - 2/(ex2(d * 2/ln2) + 1); exact saturation at +/-inf.
__device__ __forceinline__ float fast_tanh(float d)
{
    float e;
    asm("ex2.approx.f32 %0, %1;" : "=f"(e) : "f"(d * 2.885390081777927f));
    float r;
    asm("rcp.approx.f32 %0, %1;" : "=f"(r) : "f"(e + 1.0f));
    return fmaf(-2.0f, r, 1.0f);
}

__device__ __forceinline__ void process_row(const float* __restrict__ xr,
                                            float* __restrict__ orow,
                                            unsigned lane)
{
    const int lbase = (int)lane * LPT;

    // Prefetch chunks 0 and 1 (depth-2 pipeline).
    float4 a0 = __ldcs(reinterpret_cast<const float4*>(xr + lbase));
    float4 b0 = __ldcs(reinterpret_cast<const float4*>(xr + lbase + 4));
    float4 a1 = __ldcs(reinterpret_cast<const float4*>(xr + CHUNK + lbase));
    float4 b1 = __ldcs(reinterpret_cast<const float4*>(xr + CHUNK + lbase + 4));

    float carry      = 0.0f;
    float chunk_last = 0.0f;

#pragma unroll 1
    for (int ch = 0; ch < NCHUNK; ch++) {
        // Prefetch chunk ch+2 before any compute of chunk ch.
        float4 na = make_float4(0.f, 0.f, 0.f, 0.f);
        float4 nb = na;
        if (ch + 2 < NCHUNK) {
            const float* pn = xr + (ch + 2) * CHUNK + lbase;
            na = __ldcs(reinterpret_cast<const float4*>(pn));
            nb = __ldcs(reinterpret_cast<const float4*>(pn + 4));
        }

        float v[LPT] = {a0.x, a0.y, a0.z, a0.w, b0.x, b0.y, b0.z, b0.w};

        // Neighbor for this lane's first diff.
        float prev = __shfl_up_sync(0xffffffffu, v[LPT - 1], 1);
        if (lane == 0u) prev = (ch == 0) ? v[0] : chunk_last;

        // Lane-local inclusive scan of tanh(diffs). The 8 tanhs are
        // independent; only the adds chain.
        float s[LPT];
        float run = 0.0f, p = prev;
#pragma unroll
        for (int i = 0; i < LPT; i++) {
            run += fast_tanh(v[i] - p);
            p = v[i];
            s[i] = run;
        }
        const float tot = run;

        // Warp inclusive scan of lane totals.
        float ws = tot;
#pragma unroll
        for (int off = 1; off < 32; off <<= 1) {
            float n = __shfl_up_sync(0xffffffffu, ws, off);
            if (lane >= (unsigned)off) ws += n;
        }

        const float prefix = carry + (ws - tot);   // exclusive for this lane

        float* po = orow + ch * CHUNK + lbase;
        __stcs(reinterpret_cast<float4*>(po),
               make_float4(prefix + s[0], prefix + s[1], prefix + s[2], prefix + s[3]));
        __stcs(reinterpret_cast<float4*>(po + 4),
               make_float4(prefix + s[4], prefix + s[5], prefix + s[6], prefix + s[7]));

        carry      += __shfl_sync(0xffffffffu, ws, 31);
        chunk_last  = __shfl_sync(0xffffffffu, v[LPT - 1], 31);

        // Rotate pipeline.
        a0 = a1; b0 = b1;
        a1 = na; b1 = nb;
    }
}

__global__ __launch_bounds__(THREADS, 4)
void softindex_kernel(const float* __restrict__ x, float* __restrict__ out)
{
    const unsigned lane = threadIdx.x & 31u;

    for (;;) {
        unsigned row;
        if (lane == 0u) row = atomicAdd(&g_row_ctr, 1u);
        row = __shfl_sync(0xffffffffu, row, 0);
        if (row >= (unsigned)S) return;

        process_row(x + (size_t)row * S, out + (size_t)row * S, lane);
    }
}

extern "C" void kernel_launch(void* const* d_in, const int* in_sizes, int n_in,
                              void* d_out, int out_size)
{
    const float* x = (const float*)d_in[0];
    float* out     = (float*)d_out;
    (void)in_sizes; (void)n_in; (void)out_size;

    reset_ctr_kernel<<<1, 1>>>();
    softindex_kernel<<<GRID, THREADS>>>(x, out);
}